// round 11
// baseline (speedup 1.0000x reference)
#include <cuda_runtime.h>
#include <math.h>
#include <stdint.h>

#define BB 64
#define TT 32
#define CC 2048
#define DD 1024

// Scratch (__device__ globals; allocation-free rule)
__device__ float g_XN[BB * TT * CC];   // noise-mixed input (16 MB)
__device__ float g_H [TT * BB * DD];
__device__ float g_H2[TT * BB * DD];
__device__ float g_Z [TT * BB * DD];
__device__ float g_G [TT * BB * DD];

__device__ __forceinline__ float gelu_f(float x) {
    return 0.5f * x * (1.0f + erff(x * 0.70710678118654752440f));
}

__device__ __forceinline__ uint32_t f2tf(float x) {
    uint32_t r;
    asm("cvt.rna.tf32.f32 %0, %1;" : "=r"(r) : "f"(x));
    return r;
}

// acc += A(16x8 tf32) @ B(8x8 tf32), fp32 accum
#define MMA_TF32(c, a, b) \
    asm volatile("mma.sync.aligned.m16n8k8.row.col.f32.tf32.tf32.f32 " \
                 "{%0,%1,%2,%3}, {%4,%5,%6,%7}, {%8,%9}, {%0,%1,%2,%3};" \
                 : "+f"((c)[0]), "+f"((c)[1]), "+f"((c)[2]), "+f"((c)[3]) \
                 : "r"((a)[0]), "r"((a)[1]), "r"((a)[2]), "r"((a)[3]), \
                   "r"((b)[0]), "r"((b)[1]))

// smem word offsets
// A frag-major: 16 blocks (B=(wm*2+mt)*4+ks) * 136 words; inner per block:
//   g*16 + (tg^(g>>1))*4 + kh*2 + mh   (128 data words + 8 pad)
#define AHI_OFF 0
#define ALO_OFF 2176            // 16*136
#define WHI_OFF 4352            // W: [k][n] row-major, pad 136
#define WLO_OFF 8704            // + 32*136
#define SM_WORDS 13056          // 52224 bytes
#define W_PAD 136
#define C_PAD 132

// ---------------------------------------------------------------------------
// Batched GEMM via 3xTF32 mma.sync: C[t](64 x N) = Act[t](64 x K) @ W[t](K x N)
// Block: 256 thr, tile 64m x 128n, BK=32, register-prefetch double buffering.
// Warp (wm=wid&1, wn=wid>>1): 32m x 32n via m16n8k8, 2 m-frags x 4 n-frags.
// ---------------------------------------------------------------------------
template<bool GELU_EPI>
__global__ __launch_bounds__(256) void gemm_mma(
    const float* __restrict__ Act, long act_t, int act_ld,
    const float* __restrict__ W, int N, int K,
    float* __restrict__ C, long c_t, int c_ld)
{
    extern __shared__ __align__(16) uint32_t sm[];
    const int t     = blockIdx.y;
    const int ntile = blockIdx.x;
    const int tid   = threadIdx.x;
    const int wid   = tid >> 5;
    const int lid   = tid & 31;
    const int wm    = wid & 1;
    const int wn    = wid >> 1;
    const int g     = lid >> 2;
    const int tg    = lid & 3;
    const int gsw   = g >> 1;              // xor swizzle term

    const float* At = Act + (long)t * act_t;
    const float* Wt = W + (long)t * K * N + ntile * 128;

    float acc[2][4][4];
    #pragma unroll
    for (int i = 0; i < 2; i++)
        #pragma unroll
        for (int j = 0; j < 4; j++)
            #pragma unroll
            for (int r = 0; r < 4; r++) acc[i][j][r] = 0.f;

    // global load maps
    const int s_ar = tid >> 2;             // A row 0..63
    const int s_ak = (tid & 3) * 8;        // A k base (8 floats)
    const int s_wk = tid >> 3;             // W k row 0..31
    const int s_wn = (tid & 7) * 16;       // W n base (16 floats)

    // A staging address precompute (frag-major layout)
    const int a_wm = s_ar >> 5, a_mt = (s_ar >> 4) & 1;
    const int a_mh = (s_ar >> 3) & 1, a_g = s_ar & 7;
    const int a_ks = tid & 3;
    const int a_base = ((a_wm * 2 + a_mt) * 4 + a_ks) * 136 + a_g * 16 + a_mh;
    const int a_sw   = a_g >> 1;

    // compute-side A v4 base (runtime part)
    const int a_ld_base = g * 16 + ((tg ^ gsw) << 2);

    // ---- prefetch chunk 0
    float4 va0, va1, vw[4];
    {
        const float* ap = At + (long)s_ar * act_ld + s_ak;
        va0 = *(const float4*)(ap);
        va1 = *(const float4*)(ap + 4);
        const float* wp = Wt + (long)s_wk * N + s_wn;
        #pragma unroll
        for (int q = 0; q < 4; q++) vw[q] = *(const float4*)(wp + q * 4);
    }

    for (int kc = 0; kc < K; kc += 32) {
        // ---- stage A from regs (hi/lo tf32, frag-major scatter)
        #pragma unroll
        for (int j = 0; j < 8; j++) {
            float x = (j < 4) ? (&va0.x)[j] : (&va1.x)[j - 4];
            uint32_t h = f2tf(x);
            int off = a_base + (((j & 3) ^ a_sw) << 2) + ((j >> 2) << 1);
            sm[AHI_OFF + off] = h;
            sm[ALO_OFF + off] = f2tf(x - __uint_as_float(h));
        }
        // ---- stage W from regs (hi/lo tf32, row-major v4 stores)
        {
            int wrow = s_wk * W_PAD + s_wn;
            #pragma unroll
            for (int q = 0; q < 4; q++) {
                uint4 hh, ll;
                uint32_t* hp = &hh.x; uint32_t* lp = &ll.x;
                #pragma unroll
                for (int j = 0; j < 4; j++) {
                    float x = (&vw[q].x)[j];
                    uint32_t h = f2tf(x);
                    hp[j] = h;
                    lp[j] = f2tf(x - __uint_as_float(h));
                }
                *(uint4*)(sm + WHI_OFF + wrow + q * 4) = hh;
                *(uint4*)(sm + WLO_OFF + wrow + q * 4) = ll;
            }
        }
        __syncthreads();

        // ---- prefetch next chunk (overlaps compute below)
        if (kc + 32 < K) {
            const float* ap = At + (long)s_ar * act_ld + kc + 32 + s_ak;
            va0 = *(const float4*)(ap);
            va1 = *(const float4*)(ap + 4);
            const float* wp = Wt + (long)(kc + 32 + s_wk) * N + s_wn;
            #pragma unroll
            for (int q = 0; q < 4; q++) vw[q] = *(const float4*)(wp + q * 4);
        }

        // ---- compute: 4 k-steps of 8
        #pragma unroll
        for (int ks = 0; ks < 4; ks++) {
            // A frags: v4 loads, conflict-free
            uint4 ahi[2], alo[2];
            #pragma unroll
            for (int mt = 0; mt < 2; mt++) {
                int blk = ((wm * 2 + mt) * 4 + ks) * 136 + a_ld_base;
                ahi[mt] = *(const uint4*)(sm + AHI_OFF + blk);
                alo[mt] = *(const uint4*)(sm + ALO_OFF + blk);
            }
            // B frags: scalar loads, conflict-free (bank = 8*tg + g + 8*nt)
            uint32_t bhi[4][2], blo[4][2];
            #pragma unroll
            for (int nt = 0; nt < 4; nt++) {
                int n = wn * 32 + nt * 8 + g;
                int i0 = (ks * 8 + tg) * W_PAD + n;
                int i1 = i0 + 4 * W_PAD;
                bhi[nt][0] = sm[WHI_OFF + i0];
                bhi[nt][1] = sm[WHI_OFF + i1];
                blo[nt][0] = sm[WLO_OFF + i0];
                blo[nt][1] = sm[WLO_OFF + i1];
            }
            #pragma unroll
            for (int mt = 0; mt < 2; mt++) {
                const uint32_t* ah = (const uint32_t*)&ahi[mt];
                const uint32_t* al = (const uint32_t*)&alo[mt];
                #pragma unroll
                for (int nt = 0; nt < 4; nt++) {
                    MMA_TF32(acc[mt][nt], ah, bhi[nt]);
                    MMA_TF32(acc[mt][nt], ah, blo[nt]);
                    MMA_TF32(acc[mt][nt], al, bhi[nt]);
                }
            }
        }
        __syncthreads();
    }

    // ---- epilogue: stage C (64 x 128) in smem for coalesced stores
    float* Csm = (float*)sm;               // [64][C_PAD]
    #pragma unroll
    for (int mt = 0; mt < 2; mt++) {
        #pragma unroll
        for (int nt = 0; nt < 4; nt++) {
            int row = wm * 32 + mt * 16 + g;
            int col = wn * 32 + nt * 8 + 2 * tg;
            float v0 = acc[mt][nt][0], v1 = acc[mt][nt][1];
            float v2 = acc[mt][nt][2], v3 = acc[mt][nt][3];
            if (GELU_EPI) {
                v0 = gelu_f(v0); v1 = gelu_f(v1);
                v2 = gelu_f(v2); v3 = gelu_f(v3);
            }
            *(float2*)(Csm + row * C_PAD + col)       = make_float2(v0, v1);
            *(float2*)(Csm + (row + 8) * C_PAD + col) = make_float2(v2, v3);
        }
    }
    __syncthreads();

    float* Cg = C + (long)t * c_t + ntile * 128;
    #pragma unroll
    for (int i = 0; i < 8; i++) {
        int idx = tid + i * 256;           // 2048 float4
        int b = idx >> 5, c4 = idx & 31;
        float4 v = *(float4*)(Csm + b * C_PAD + c4 * 4);
        *(float4*)(Cg + (long)b * c_ld + c4 * 4) = v;
    }
}

// ---------------------------------------------------------------------------
// Noise-mix pre-pass: xn = noise_x * 1e-4 + x * (1 - 1e-4)
// ---------------------------------------------------------------------------
__global__ __launch_bounds__(256) void mix_kernel(
    const float* __restrict__ x, const float* __restrict__ nx,
    float* __restrict__ xn, int n4)
{
    int i = blockIdx.x * 256 + threadIdx.x;
    if (i >= n4) return;
    float4 a = reinterpret_cast<const float4*>(x)[i];
    float4 b = reinterpret_cast<const float4*>(nx)[i];
    const float f = 1e-4f, g = 1.0f - 1e-4f;
    float4 o;
    o.x = b.x * f + a.x * g;
    o.y = b.y * f + a.y * g;
    o.z = b.z * f + a.z * g;
    o.w = b.w * f + a.w * g;
    reinterpret_cast<float4*>(xn)[i] = o;
}

// ---------------------------------------------------------------------------
// Fused LayerNorm + latent noise + clamp. One block per row r=t*BB+b, D=1024.
// noise_z layout is [b][t][d].
// ---------------------------------------------------------------------------
__global__ __launch_bounds__(256) void ln_kernel(
    const float* __restrict__ H2, const float* __restrict__ noise_z,
    const float* __restrict__ gamma, const float* __restrict__ beta,
    float* __restrict__ Z)
{
    const int r = blockIdx.x;
    const int t = r >> 6;
    const int b = r & 63;
    const int tid = threadIdx.x;

    const float* h  = H2 + (long)r * DD;
    const float* nz = noise_z + ((long)b * TT + t) * DD;
    float*       z  = Z + (long)r * DD;

    float4 hv = *reinterpret_cast<const float4*>(h + tid * 4);
    float s  = hv.x + hv.y + hv.z + hv.w;
    float ss = hv.x * hv.x + hv.y * hv.y + hv.z * hv.z + hv.w * hv.w;

    #pragma unroll
    for (int off = 16; off > 0; off >>= 1) {
        s  += __shfl_xor_sync(0xffffffffu, s,  off);
        ss += __shfl_xor_sync(0xffffffffu, ss, off);
    }
    __shared__ float ws[8], wss[8];
    const int lane = tid & 31, wrp = tid >> 5;
    if (lane == 0) { ws[wrp] = s; wss[wrp] = ss; }
    __syncthreads();

    float mu = 0.f, m2 = 0.f;
    #pragma unroll
    for (int i = 0; i < 8; i++) { mu += ws[i]; m2 += wss[i]; }
    mu *= (1.0f / DD);
    float var  = m2 * (1.0f / DD) - mu * mu;
    float rstd = rsqrtf(var + 1e-5f);

    float4 nv = *reinterpret_cast<const float4*>(nz + tid * 4);
    float4 g4 = *reinterpret_cast<const float4*>(gamma + tid * 4);
    float4 b4 = *reinterpret_cast<const float4*>(beta + tid * 4);

    const float fl = 1e-3f, gl = 1.0f - 1e-3f;
    float4 ov; float v;
    v = (hv.x - mu) * rstd * g4.x + b4.x; v = nv.x * fl + v * gl; ov.x = fminf(1.0f, fmaxf(-1.0f, v));
    v = (hv.y - mu) * rstd * g4.y + b4.y; v = nv.y * fl + v * gl; ov.y = fminf(1.0f, fmaxf(-1.0f, v));
    v = (hv.z - mu) * rstd * g4.z + b4.z; v = nv.z * fl + v * gl; ov.z = fminf(1.0f, fmaxf(-1.0f, v));
    v = (hv.w - mu) * rstd * g4.w + b4.w; v = nv.w * fl + v * gl; ov.w = fminf(1.0f, fmaxf(-1.0f, v));
    *reinterpret_cast<float4*>(z + tid * 4) = ov;
}

extern "C" void kernel_launch(void* const* d_in, const int* in_sizes, int n_in,
                              void* d_out, int out_size) {
    const float* x       = (const float*)d_in[0];
    const float* noise_x = (const float*)d_in[1];
    const float* noise_z = (const float*)d_in[2];
    const float* enc_w1  = (const float*)d_in[3];   // [T][C][D]
    const float* enc_w2  = (const float*)d_in[4];   // [T][D][D]
    const float* dec_w1  = (const float*)d_in[5];   // [T][D][D]
    const float* dec_w2  = (const float*)d_in[6];   // [T][D][C]
    const float* ln_g    = (const float*)d_in[7];
    const float* ln_b    = (const float*)d_in[8];
    float* out = (float*)d_out;

    float *XN, *H, *H2, *Z, *G;
    cudaGetSymbolAddress((void**)&XN, g_XN);
    cudaGetSymbolAddress((void**)&H,  g_H);
    cudaGetSymbolAddress((void**)&H2, g_H2);
    cudaGetSymbolAddress((void**)&Z,  g_Z);
    cudaGetSymbolAddress((void**)&G,  g_G);

    const int smem_bytes = SM_WORDS * 4;   // 52224
    cudaFuncSetAttribute(gemm_mma<true>,  cudaFuncAttributeMaxDynamicSharedMemorySize, smem_bytes);
    cudaFuncSetAttribute(gemm_mma<false>, cudaFuncAttributeMaxDynamicSharedMemorySize, smem_bytes);

    // 0) noise-mix x
    {
        int n4 = BB * TT * CC / 4;
        mix_kernel<<<n4 / 256, 256>>>(x, noise_x, XN, n4);
    }

    // 1) enc1: H = gelu(XN_chunk @ enc_w1[t])   K=2048, N=1024
    gemm_mma<true><<<dim3(DD / 128, TT), 256, smem_bytes>>>(
        XN, (long)CC, TT * CC, enc_w1, DD, CC, H, (long)BB * DD, DD);

    // 2) enc2: H2 = H @ enc_w2[t]               K=1024, N=1024
    gemm_mma<false><<<dim3(DD / 128, TT), 256, smem_bytes>>>(
        H, (long)BB * DD, DD, enc_w2, DD, DD, H2, (long)BB * DD, DD);

    // 3) LayerNorm + latent noise + clamp
    ln_kernel<<<TT * BB, 256>>>(H2, noise_z, ln_g, ln_b, Z);

    // 4) dec1: G = gelu(Z @ dec_w1[t])           K=1024, N=1024
    gemm_mma<true><<<dim3(DD / 128, TT), 256, smem_bytes>>>(
        Z, (long)BB * DD, DD, dec_w1, DD, DD, G, (long)BB * DD, DD);

    // 5) dec2: out = G @ dec_w2[t]               K=1024, N=2048
    gemm_mma<false><<<dim3(CC / 128, TT), 256, smem_bytes>>>(
        G, (long)BB * DD, DD, dec_w2, CC, DD, out, (long)CC, TT * CC);
}

// round 12
// speedup vs baseline: 1.9407x; 1.9407x over previous
#include <cuda_runtime.h>
#include <cuda_bf16.h>
#include <math.h>
#include <stdint.h>

#define BB 64
#define TT 32
#define CC 2048
#define DD 1024

// Scratch (__device__ globals; allocation-free rule)
__device__ float g_XN[BB * TT * CC];   // noise-mixed input (16 MB)
__device__ float g_H [TT * BB * DD];
__device__ float g_H2[TT * BB * DD];
__device__ float g_Z [TT * BB * DD];
__device__ float g_G [TT * BB * DD];

__device__ __forceinline__ float gelu_f(float x) {
    return 0.5f * x * (1.0f + erff(x * 0.70710678118654752440f));
}

// pack two floats -> bf16x2 word: lo16 = bf16(e), hi16 = bf16(o)
__device__ __forceinline__ uint32_t pkbf(float o, float e) {
    uint32_t r;
    asm("cvt.rn.bf16x2.f32 %0, %1, %2;" : "=r"(r) : "f"(o), "f"(e));
    return r;
}
// unpack bf16x2 word -> two floats (e = lo half, o = hi half)
__device__ __forceinline__ float2 upbf(uint32_t w) {
    __nv_bfloat162 h = *reinterpret_cast<__nv_bfloat162*>(&w);
    return __bfloat1622float2(h);
}

// acc += A(16x16 bf16) @ B(16x8 bf16), fp32 accum
#define MMA_BF16(c, a0, a1, a2, a3, b0, b1) \
    asm volatile("mma.sync.aligned.m16n8k16.row.col.f32.bf16.bf16.f32 " \
                 "{%0,%1,%2,%3}, {%4,%5,%6,%7}, {%8,%9}, {%0,%1,%2,%3};" \
                 : "+f"((c)[0]), "+f"((c)[1]), "+f"((c)[2]), "+f"((c)[3]) \
                 : "r"(a0), "r"(a1), "r"(a2), "r"(a3), "r"(b0), "r"(b1))

// smem word offsets (32-bit words). A: [16 k-pairs][72] bf16x2, W: [16][136].
#define AHI_OFF 0
#define ALO_OFF 1152           // 16*72
#define WHI_OFF 2304
#define WLO_OFF 4480           // + 16*136
#define SM_WORDS 8448          // max(6656 operand, 64*132 epilogue) words
#define A2_PAD 72
#define W2_PAD 136
#define C_PAD 132

// ---------------------------------------------------------------------------
// Batched GEMM via 3x-split bf16 mma.sync m16n8k16:
//   C[t](64 x N) = Act[t](64 x K) @ W[t](K x N)
// Block: 256 thr, tile 64m x 128n, BK=32 (2 k16-steps), register prefetch.
// Warp (wm=wid&1, wn=wid>>1): 32m x 32n, 2 m-frags x 4 n-frags.
// Split: x = bf16(x) + bf16(x - bf16(x)); products hh + hl + lh.
// ---------------------------------------------------------------------------
template<bool GELU_EPI>
__global__ __launch_bounds__(256) void gemm_mma(
    const float* __restrict__ Act, long act_t, int act_ld,
    const float* __restrict__ W, int N, int K,
    float* __restrict__ C, long c_t, int c_ld)
{
    extern __shared__ __align__(16) uint32_t sm[];
    const int t     = blockIdx.y;
    const int ntile = blockIdx.x;
    const int tid   = threadIdx.x;
    const int wid   = tid >> 5;
    const int lid   = tid & 31;
    const int wm    = wid & 1;
    const int wn    = wid >> 1;
    const int g     = lid >> 2;
    const int tg    = lid & 3;

    const float* At = Act + (long)t * act_t;
    const float* Wt = W + (long)t * K * N + ntile * 128;

    float acc[2][4][4];
    #pragma unroll
    for (int i = 0; i < 2; i++)
        #pragma unroll
        for (int j = 0; j < 4; j++)
            #pragma unroll
            for (int r = 0; r < 4; r++) acc[i][j][r] = 0.f;

    // global load maps
    const int s_ar = tid >> 2;             // A row 0..63
    const int s_ak = (tid & 3) * 8;        // A k base (8 floats = 4 pairs)
    const int s_wp = tid >> 4;             // W k-pair 0..15 (rows 2p, 2p+1)
    const int s_wn = (tid & 15) * 8;       // W n base (8 floats)

    // ---- prefetch chunk 0
    float4 va0, va1, we0, we1, wo0, wo1;
    {
        const float* ap = At + (long)s_ar * act_ld + s_ak;
        va0 = *(const float4*)(ap);
        va1 = *(const float4*)(ap + 4);
        const float* wp = Wt + (long)(2 * s_wp) * N + s_wn;
        we0 = *(const float4*)(wp);
        we1 = *(const float4*)(wp + 4);
        wo0 = *(const float4*)(wp + N);
        wo1 = *(const float4*)(wp + N + 4);
    }

    const int a_jb = s_ak >> 1;            // A k-pair base 0,4,8,12

    for (int kc = 0; kc < K; kc += 32) {
        // ---- stage A (hi/lo bf16x2, [pair][m]), j rotated by tg to avoid
        //      4-way store conflicts
        {
            float xs[8] = {va0.x, va0.y, va0.z, va0.w, va1.x, va1.y, va1.z, va1.w};
            #pragma unroll
            for (int jj = 0; jj < 4; jj++) {
                int j = (jj + tg) & 3;
                float e = xs[2 * j], o = xs[2 * j + 1];
                uint32_t h = pkbf(o, e);
                float2 hf = upbf(h);
                uint32_t l = pkbf(o - hf.y, e - hf.x);
                int off = (a_jb + j) * A2_PAD + s_ar;
                sm[AHI_OFF + off] = h;
                sm[ALO_OFF + off] = l;
            }
        }
        // ---- stage W (hi/lo bf16x2, [pair][n]), v4 stores
        {
            uint4 hh0, hh1, ll0, ll1;
            uint32_t* h0 = &hh0.x; uint32_t* h1 = &hh1.x;
            uint32_t* l0 = &ll0.x; uint32_t* l1 = &ll1.x;
            #pragma unroll
            for (int j = 0; j < 4; j++) {
                float e = (&we0.x)[j], o = (&wo0.x)[j];
                uint32_t h = pkbf(o, e);
                float2 hf = upbf(h);
                h0[j] = h;
                l0[j] = pkbf(o - hf.y, e - hf.x);
            }
            #pragma unroll
            for (int j = 0; j < 4; j++) {
                float e = (&we1.x)[j], o = (&wo1.x)[j];
                uint32_t h = pkbf(o, e);
                float2 hf = upbf(h);
                h1[j] = h;
                l1[j] = pkbf(o - hf.y, e - hf.x);
            }
            int wrow = s_wp * W2_PAD + s_wn;
            *(uint4*)(sm + WHI_OFF + wrow)     = hh0;
            *(uint4*)(sm + WHI_OFF + wrow + 4) = hh1;
            *(uint4*)(sm + WLO_OFF + wrow)     = ll0;
            *(uint4*)(sm + WLO_OFF + wrow + 4) = ll1;
        }
        __syncthreads();

        // ---- prefetch next chunk (overlaps compute)
        if (kc + 32 < K) {
            const float* ap = At + (long)s_ar * act_ld + kc + 32 + s_ak;
            va0 = *(const float4*)(ap);
            va1 = *(const float4*)(ap + 4);
            const float* wp = Wt + (long)(kc + 32 + 2 * s_wp) * N + s_wn;
            we0 = *(const float4*)(wp);
            we1 = *(const float4*)(wp + 4);
            wo0 = *(const float4*)(wp + N);
            wo1 = *(const float4*)(wp + N + 4);
        }

        // ---- compute: 2 k16-steps
        #pragma unroll
        for (int ks = 0; ks < 2; ks++) {
            const int p0 = ks * 8 + tg;        // pairs for a0/a1, b0
            const int p1 = p0 + 4;             // pairs for a2/a3, b1
            uint32_t ah[2][4], al[2][4];
            #pragma unroll
            for (int mt = 0; mt < 2; mt++) {
                int m = wm * 32 + mt * 16 + g;
                ah[mt][0] = sm[AHI_OFF + p0 * A2_PAD + m];
                ah[mt][1] = sm[AHI_OFF + p0 * A2_PAD + m + 8];
                ah[mt][2] = sm[AHI_OFF + p1 * A2_PAD + m];
                ah[mt][3] = sm[AHI_OFF + p1 * A2_PAD + m + 8];
                al[mt][0] = sm[ALO_OFF + p0 * A2_PAD + m];
                al[mt][1] = sm[ALO_OFF + p0 * A2_PAD + m + 8];
                al[mt][2] = sm[ALO_OFF + p1 * A2_PAD + m];
                al[mt][3] = sm[ALO_OFF + p1 * A2_PAD + m + 8];
            }
            uint32_t bh[4][2], bl[4][2];
            #pragma unroll
            for (int nt = 0; nt < 4; nt++) {
                int n = wn * 32 + nt * 8 + g;
                bh[nt][0] = sm[WHI_OFF + p0 * W2_PAD + n];
                bh[nt][1] = sm[WHI_OFF + p1 * W2_PAD + n];
                bl[nt][0] = sm[WLO_OFF + p0 * W2_PAD + n];
                bl[nt][1] = sm[WLO_OFF + p1 * W2_PAD + n];
            }
            #pragma unroll
            for (int mt = 0; mt < 2; mt++)
                #pragma unroll
                for (int nt = 0; nt < 4; nt++) {
                    MMA_BF16(acc[mt][nt], ah[mt][0], ah[mt][1], ah[mt][2], ah[mt][3],
                             bh[nt][0], bh[nt][1]);
                    MMA_BF16(acc[mt][nt], ah[mt][0], ah[mt][1], ah[mt][2], ah[mt][3],
                             bl[nt][0], bl[nt][1]);
                    MMA_BF16(acc[mt][nt], al[mt][0], al[mt][1], al[mt][2], al[mt][3],
                             bh[nt][0], bh[nt][1]);
                }
        }
        __syncthreads();
    }

    // ---- epilogue: stage C (64 x 128) in smem for coalesced stores
    float* Csm = (float*)sm;               // [64][C_PAD]
    #pragma unroll
    for (int mt = 0; mt < 2; mt++) {
        #pragma unroll
        for (int nt = 0; nt < 4; nt++) {
            int row = wm * 32 + mt * 16 + g;
            int col = wn * 32 + nt * 8 + 2 * tg;
            float v0 = acc[mt][nt][0], v1 = acc[mt][nt][1];
            float v2 = acc[mt][nt][2], v3 = acc[mt][nt][3];
            if (GELU_EPI) {
                v0 = gelu_f(v0); v1 = gelu_f(v1);
                v2 = gelu_f(v2); v3 = gelu_f(v3);
            }
            *(float2*)(Csm + row * C_PAD + col)       = make_float2(v0, v1);
            *(float2*)(Csm + (row + 8) * C_PAD + col) = make_float2(v2, v3);
        }
    }
    __syncthreads();

    float* Cg = C + (long)t * c_t + ntile * 128;
    #pragma unroll
    for (int i = 0; i < 8; i++) {
        int idx = tid + i * 256;           // 2048 float4
        int b = idx >> 5, c4 = idx & 31;
        float4 v = *(float4*)(Csm + b * C_PAD + c4 * 4);
        *(float4*)(Cg + (long)b * c_ld + c4 * 4) = v;
    }
}

// ---------------------------------------------------------------------------
// Noise-mix pre-pass: xn = noise_x * 1e-4 + x * (1 - 1e-4)
// ---------------------------------------------------------------------------
__global__ __launch_bounds__(256) void mix_kernel(
    const float* __restrict__ x, const float* __restrict__ nx,
    float* __restrict__ xn, int n4)
{
    int i = blockIdx.x * 256 + threadIdx.x;
    if (i >= n4) return;
    float4 a = reinterpret_cast<const float4*>(x)[i];
    float4 b = reinterpret_cast<const float4*>(nx)[i];
    const float f = 1e-4f, g = 1.0f - 1e-4f;
    float4 o;
    o.x = b.x * f + a.x * g;
    o.y = b.y * f + a.y * g;
    o.z = b.z * f + a.z * g;
    o.w = b.w * f + a.w * g;
    reinterpret_cast<float4*>(xn)[i] = o;
}

// ---------------------------------------------------------------------------
// Fused LayerNorm + latent noise + clamp. One block per row r=t*BB+b, D=1024.
// noise_z layout is [b][t][d].
// ---------------------------------------------------------------------------
__global__ __launch_bounds__(256) void ln_kernel(
    const float* __restrict__ H2, const float* __restrict__ noise_z,
    const float* __restrict__ gamma, const float* __restrict__ beta,
    float* __restrict__ Z)
{
    const int r = blockIdx.x;
    const int t = r >> 6;
    const int b = r & 63;
    const int tid = threadIdx.x;

    const float* h  = H2 + (long)r * DD;
    const float* nz = noise_z + ((long)b * TT + t) * DD;
    float*       z  = Z + (long)r * DD;

    float4 hv = *reinterpret_cast<const float4*>(h + tid * 4);
    float s  = hv.x + hv.y + hv.z + hv.w;
    float ss = hv.x * hv.x + hv.y * hv.y + hv.z * hv.z + hv.w * hv.w;

    #pragma unroll
    for (int off = 16; off > 0; off >>= 1) {
        s  += __shfl_xor_sync(0xffffffffu, s,  off);
        ss += __shfl_xor_sync(0xffffffffu, ss, off);
    }
    __shared__ float ws[8], wss[8];
    const int lane = tid & 31, wrp = tid >> 5;
    if (lane == 0) { ws[wrp] = s; wss[wrp] = ss; }
    __syncthreads();

    float mu = 0.f, m2 = 0.f;
    #pragma unroll
    for (int i = 0; i < 8; i++) { mu += ws[i]; m2 += wss[i]; }
    mu *= (1.0f / DD);
    float var  = m2 * (1.0f / DD) - mu * mu;
    float rstd = rsqrtf(var + 1e-5f);

    float4 nv = *reinterpret_cast<const float4*>(nz + tid * 4);
    float4 g4 = *reinterpret_cast<const float4*>(gamma + tid * 4);
    float4 b4 = *reinterpret_cast<const float4*>(beta + tid * 4);

    const float fl = 1e-3f, gl = 1.0f - 1e-3f;
    float4 ov; float v;
    v = (hv.x - mu) * rstd * g4.x + b4.x; v = nv.x * fl + v * gl; ov.x = fminf(1.0f, fmaxf(-1.0f, v));
    v = (hv.y - mu) * rstd * g4.y + b4.y; v = nv.y * fl + v * gl; ov.y = fminf(1.0f, fmaxf(-1.0f, v));
    v = (hv.z - mu) * rstd * g4.z + b4.z; v = nv.z * fl + v * gl; ov.z = fminf(1.0f, fmaxf(-1.0f, v));
    v = (hv.w - mu) * rstd * g4.w + b4.w; v = nv.w * fl + v * gl; ov.w = fminf(1.0f, fmaxf(-1.0f, v));
    *reinterpret_cast<float4*>(z + tid * 4) = ov;
}

extern "C" void kernel_launch(void* const* d_in, const int* in_sizes, int n_in,
                              void* d_out, int out_size) {
    const float* x       = (const float*)d_in[0];
    const float* noise_x = (const float*)d_in[1];
    const float* noise_z = (const float*)d_in[2];
    const float* enc_w1  = (const float*)d_in[3];   // [T][C][D]
    const float* enc_w2  = (const float*)d_in[4];   // [T][D][D]
    const float* dec_w1  = (const float*)d_in[5];   // [T][D][D]
    const float* dec_w2  = (const float*)d_in[6];   // [T][D][C]
    const float* ln_g    = (const float*)d_in[7];
    const float* ln_b    = (const float*)d_in[8];
    float* out = (float*)d_out;

    float *XN, *H, *H2, *Z, *G;
    cudaGetSymbolAddress((void**)&XN, g_XN);
    cudaGetSymbolAddress((void**)&H,  g_H);
    cudaGetSymbolAddress((void**)&H2, g_H2);
    cudaGetSymbolAddress((void**)&Z,  g_Z);
    cudaGetSymbolAddress((void**)&G,  g_G);

    const int smem_bytes = SM_WORDS * 4;   // 33792
    cudaFuncSetAttribute(gemm_mma<true>,  cudaFuncAttributeMaxDynamicSharedMemorySize, smem_bytes);
    cudaFuncSetAttribute(gemm_mma<false>, cudaFuncAttributeMaxDynamicSharedMemorySize, smem_bytes);

    // 0) noise-mix x
    {
        int n4 = BB * TT * CC / 4;
        mix_kernel<<<n4 / 256, 256>>>(x, noise_x, XN, n4);
    }

    // 1) enc1: H = gelu(XN_chunk @ enc_w1[t])   K=2048, N=1024
    gemm_mma<true><<<dim3(DD / 128, TT), 256, smem_bytes>>>(
        XN, (long)CC, TT * CC, enc_w1, DD, CC, H, (long)BB * DD, DD);

    // 2) enc2: H2 = H @ enc_w2[t]               K=1024, N=1024
    gemm_mma<false><<<dim3(DD / 128, TT), 256, smem_bytes>>>(
        H, (long)BB * DD, DD, enc_w2, DD, DD, H2, (long)BB * DD, DD);

    // 3) LayerNorm + latent noise + clamp
    ln_kernel<<<TT * BB, 256>>>(H2, noise_z, ln_g, ln_b, Z);

    // 4) dec1: G = gelu(Z @ dec_w1[t])           K=1024, N=1024
    gemm_mma<true><<<dim3(DD / 128, TT), 256, smem_bytes>>>(
        Z, (long)BB * DD, DD, dec_w1, DD, DD, G, (long)BB * DD, DD);

    // 5) dec2: out = G @ dec_w2[t]               K=1024, N=2048
    gemm_mma<false><<<dim3(CC / 128, TT), 256, smem_bytes>>>(
        G, (long)BB * DD, DD, dec_w2, CC, DD, out, (long)CC, TT * CC);
}

// round 13
// speedup vs baseline: 2.1718x; 1.1191x over previous
#include <cuda_runtime.h>
#include <cuda_bf16.h>
#include <math.h>
#include <stdint.h>

#define BB 64
#define TT 32
#define CC 2048
#define DD 1024

// Scratch (__device__ globals; allocation-free rule)
__device__ float g_XN[BB * TT * CC];   // noise-mixed input (16 MB)
__device__ float g_H [TT * BB * DD];
__device__ float g_H2[TT * BB * DD];
__device__ float g_Z [TT * BB * DD];
__device__ float g_G [TT * BB * DD];

__device__ __forceinline__ float gelu_f(float x) {
    return 0.5f * x * (1.0f + erff(x * 0.70710678118654752440f));
}

// pack two floats -> bf16x2 word: lo16 = bf16(e), hi16 = bf16(o)
__device__ __forceinline__ uint32_t pkbf(float o, float e) {
    uint32_t r;
    asm("cvt.rn.bf16x2.f32 %0, %1, %2;" : "=r"(r) : "f"(o), "f"(e));
    return r;
}
// unpack bf16x2 word -> two floats (e = lo half, o = hi half)
__device__ __forceinline__ float2 upbf(uint32_t w) {
    __nv_bfloat162 h = *reinterpret_cast<__nv_bfloat162*>(&w);
    return __bfloat1622float2(h);
}

// acc += A(16x16 bf16) @ B(16x8 bf16), fp32 accum
#define MMA_BF16(c, a0, a1, a2, a3, b0, b1) \
    asm volatile("mma.sync.aligned.m16n8k16.row.col.f32.bf16.bf16.f32 " \
                 "{%0,%1,%2,%3}, {%4,%5,%6,%7}, {%8,%9}, {%0,%1,%2,%3};" \
                 : "+f"((c)[0]), "+f"((c)[1]), "+f"((c)[2]), "+f"((c)[3]) \
                 : "r"(a0), "r"(a1), "r"(a2), "r"(a3), "r"(b0), "r"(b1))

// Per-stage layout (32-bit words): A hi [16][72], A lo, W hi [16][136], W lo.
#define AHI_OFF 0
#define ALO_OFF 1152           // 16*72
#define WHI_OFF 2304
#define WLO_OFF 4480           // + 16*136
#define STAGE_WORDS 6656
#define SM_WORDS 13312         // 2 stages (epilogue 64*132=8448 fits inside)
#define A2_PAD 72
#define W2_PAD 136
#define C_PAD 132

// ---------------------------------------------------------------------------
// Batched GEMM via 3x-split bf16 mma.sync m16n8k16, double-buffered smem:
//   C[t](64 x N) = Act[t](64 x K) @ W[t](K x N)
// Block: 256 thr, tile 64m x 128n, BK=32 (2 k16-steps).
// Pipeline per chunk i: stage(buf i&1 from regs) -> sync -> prefetch regs
// (i+1) -> compute(buf i&1). Single sync/chunk; staging overlaps other
// warps' MMA phase; buffer reuse at i+2 ordered by sync at i+1.
// ---------------------------------------------------------------------------
template<bool GELU_EPI>
__global__ __launch_bounds__(256, 2) void gemm_mma(
    const float* __restrict__ Act, long act_t, int act_ld,
    const float* __restrict__ W, int N, int K,
    float* __restrict__ C, long c_t, int c_ld)
{
    extern __shared__ __align__(16) uint32_t sm[];
    const int t     = blockIdx.y;
    const int ntile = blockIdx.x;
    const int tid   = threadIdx.x;
    const int wid   = tid >> 5;
    const int lid   = tid & 31;
    const int wm    = wid & 1;
    const int wn    = wid >> 1;
    const int g     = lid >> 2;
    const int tg    = lid & 3;

    const float* At = Act + (long)t * act_t;
    const float* Wt = W + (long)t * K * N + ntile * 128;

    float acc[2][4][4];
    #pragma unroll
    for (int i = 0; i < 2; i++)
        #pragma unroll
        for (int j = 0; j < 4; j++)
            #pragma unroll
            for (int r = 0; r < 4; r++) acc[i][j][r] = 0.f;

    // global load maps
    const int s_ar = tid >> 2;             // A row 0..63
    const int s_ak = (tid & 3) * 8;        // A k base (8 floats = 4 pairs)
    const int s_wp = tid >> 4;             // W k-pair 0..15 (rows 2p, 2p+1)
    const int s_wn = (tid & 15) * 8;       // W n base (8 floats)
    const int a_jb = s_ak >> 1;            // A k-pair base 0,4,8,12

    // ---- prefetch chunk 0
    float4 va0, va1, we0, we1, wo0, wo1;
    {
        const float* ap = At + (long)s_ar * act_ld + s_ak;
        va0 = *(const float4*)(ap);
        va1 = *(const float4*)(ap + 4);
        const float* wp = Wt + (long)(2 * s_wp) * N + s_wn;
        we0 = *(const float4*)(wp);
        we1 = *(const float4*)(wp + 4);
        wo0 = *(const float4*)(wp + N);
        wo1 = *(const float4*)(wp + N + 4);
    }

    const int nch = K / 32;
    for (int i = 0; i < nch; i++) {
        uint32_t* S = sm + (i & 1) * STAGE_WORDS;

        // ---- stage A (hi/lo bf16x2, [pair][m]); j rotated by tg to avoid
        //      4-way store conflicts
        {
            float xs[8] = {va0.x, va0.y, va0.z, va0.w, va1.x, va1.y, va1.z, va1.w};
            #pragma unroll
            for (int jj = 0; jj < 4; jj++) {
                int j = (jj + tg) & 3;
                float e = xs[2 * j], o = xs[2 * j + 1];
                uint32_t h = pkbf(o, e);
                float2 hf = upbf(h);
                uint32_t l = pkbf(o - hf.y, e - hf.x);
                int off = (a_jb + j) * A2_PAD + s_ar;
                S[AHI_OFF + off] = h;
                S[ALO_OFF + off] = l;
            }
        }
        // ---- stage W (hi/lo bf16x2, [pair][n]), v4 stores
        {
            uint4 hh0, hh1, ll0, ll1;
            uint32_t* h0 = &hh0.x; uint32_t* h1 = &hh1.x;
            uint32_t* l0 = &ll0.x; uint32_t* l1 = &ll1.x;
            #pragma unroll
            for (int j = 0; j < 4; j++) {
                float e = (&we0.x)[j], o = (&wo0.x)[j];
                uint32_t h = pkbf(o, e);
                float2 hf = upbf(h);
                h0[j] = h;
                l0[j] = pkbf(o - hf.y, e - hf.x);
            }
            #pragma unroll
            for (int j = 0; j < 4; j++) {
                float e = (&we1.x)[j], o = (&wo1.x)[j];
                uint32_t h = pkbf(o, e);
                float2 hf = upbf(h);
                h1[j] = h;
                l1[j] = pkbf(o - hf.y, e - hf.x);
            }
            int wrow = s_wp * W2_PAD + s_wn;
            *(uint4*)(S + WHI_OFF + wrow)     = hh0;
            *(uint4*)(S + WHI_OFF + wrow + 4) = hh1;
            *(uint4*)(S + WLO_OFF + wrow)     = ll0;
            *(uint4*)(S + WLO_OFF + wrow + 4) = ll1;
        }
        __syncthreads();

        // ---- prefetch next chunk (overlaps compute)
        if (i + 1 < nch) {
            int kc = (i + 1) * 32;
            const float* ap = At + (long)s_ar * act_ld + kc + s_ak;
            va0 = *(const float4*)(ap);
            va1 = *(const float4*)(ap + 4);
            const float* wp = Wt + (long)(kc + 2 * s_wp) * N + s_wn;
            we0 = *(const float4*)(wp);
            we1 = *(const float4*)(wp + 4);
            wo0 = *(const float4*)(wp + N);
            wo1 = *(const float4*)(wp + N + 4);
        }

        // ---- compute: 2 k16-steps
        #pragma unroll
        for (int ks = 0; ks < 2; ks++) {
            const int p0 = ks * 8 + tg;        // pairs for a0/a1, b0
            const int p1 = p0 + 4;             // pairs for a2/a3, b1
            uint32_t ah[2][4], al[2][4];
            #pragma unroll
            for (int mt = 0; mt < 2; mt++) {
                int m = wm * 32 + mt * 16 + g;
                ah[mt][0] = S[AHI_OFF + p0 * A2_PAD + m];
                ah[mt][1] = S[AHI_OFF + p0 * A2_PAD + m + 8];
                ah[mt][2] = S[AHI_OFF + p1 * A2_PAD + m];
                ah[mt][3] = S[AHI_OFF + p1 * A2_PAD + m + 8];
                al[mt][0] = S[ALO_OFF + p0 * A2_PAD + m];
                al[mt][1] = S[ALO_OFF + p0 * A2_PAD + m + 8];
                al[mt][2] = S[ALO_OFF + p1 * A2_PAD + m];
                al[mt][3] = S[ALO_OFF + p1 * A2_PAD + m + 8];
            }
            uint32_t bh[4][2], bl[4][2];
            #pragma unroll
            for (int nt = 0; nt < 4; nt++) {
                int n = wn * 32 + nt * 8 + g;
                bh[nt][0] = S[WHI_OFF + p0 * W2_PAD + n];
                bh[nt][1] = S[WHI_OFF + p1 * W2_PAD + n];
                bl[nt][0] = S[WLO_OFF + p0 * W2_PAD + n];
                bl[nt][1] = S[WLO_OFF + p1 * W2_PAD + n];
            }
            #pragma unroll
            for (int mt = 0; mt < 2; mt++)
                #pragma unroll
                for (int nt = 0; nt < 4; nt++) {
                    MMA_BF16(acc[mt][nt], ah[mt][0], ah[mt][1], ah[mt][2], ah[mt][3],
                             bh[nt][0], bh[nt][1]);
                    MMA_BF16(acc[mt][nt], ah[mt][0], ah[mt][1], ah[mt][2], ah[mt][3],
                             bl[nt][0], bl[nt][1]);
                    MMA_BF16(acc[mt][nt], al[mt][0], al[mt][1], al[mt][2], al[mt][3],
                             bh[nt][0], bh[nt][1]);
                }
        }
        // no trailing sync: next iteration stages the other buffer; reuse of
        // this buffer (i+2) is ordered by the sync at i+1.
    }
    __syncthreads();   // all compute done before smem reuse as epilogue stage

    // ---- epilogue: stage C (64 x 128) in smem for coalesced stores
    float* Csm = (float*)sm;               // [64][C_PAD]
    #pragma unroll
    for (int mt = 0; mt < 2; mt++) {
        #pragma unroll
        for (int nt = 0; nt < 4; nt++) {
            int row = wm * 32 + mt * 16 + g;
            int col = wn * 32 + nt * 8 + 2 * tg;
            float v0 = acc[mt][nt][0], v1 = acc[mt][nt][1];
            float v2 = acc[mt][nt][2], v3 = acc[mt][nt][3];
            if (GELU_EPI) {
                v0 = gelu_f(v0); v1 = gelu_f(v1);
                v2 = gelu_f(v2); v3 = gelu_f(v3);
            }
            *(float2*)(Csm + row * C_PAD + col)       = make_float2(v0, v1);
            *(float2*)(Csm + (row + 8) * C_PAD + col) = make_float2(v2, v3);
        }
    }
    __syncthreads();

    float* Cg = C + (long)t * c_t + ntile * 128;
    #pragma unroll
    for (int i = 0; i < 8; i++) {
        int idx = tid + i * 256;           // 2048 float4
        int b = idx >> 5, c4 = idx & 31;
        float4 v = *(float4*)(Csm + b * C_PAD + c4 * 4);
        *(float4*)(Cg + (long)b * c_ld + c4 * 4) = v;
    }
}

// ---------------------------------------------------------------------------
// Noise-mix pre-pass: xn = noise_x * 1e-4 + x * (1 - 1e-4)
// ---------------------------------------------------------------------------
__global__ __launch_bounds__(256) void mix_kernel(
    const float* __restrict__ x, const float* __restrict__ nx,
    float* __restrict__ xn, int n4)
{
    int i = blockIdx.x * 256 + threadIdx.x;
    if (i >= n4) return;
    float4 a = reinterpret_cast<const float4*>(x)[i];
    float4 b = reinterpret_cast<const float4*>(nx)[i];
    const float f = 1e-4f, g = 1.0f - 1e-4f;
    float4 o;
    o.x = b.x * f + a.x * g;
    o.y = b.y * f + a.y * g;
    o.z = b.z * f + a.z * g;
    o.w = b.w * f + a.w * g;
    reinterpret_cast<float4*>(xn)[i] = o;
}

// ---------------------------------------------------------------------------
// Fused LayerNorm + latent noise + clamp. One block per row r=t*BB+b, D=1024.
// noise_z layout is [b][t][d].
// ---------------------------------------------------------------------------
__global__ __launch_bounds__(256) void ln_kernel(
    const float* __restrict__ H2, const float* __restrict__ noise_z,
    const float* __restrict__ gamma, const float* __restrict__ beta,
    float* __restrict__ Z)
{
    const int r = blockIdx.x;
    const int t = r >> 6;
    const int b = r & 63;
    const int tid = threadIdx.x;

    const float* h  = H2 + (long)r * DD;
    const float* nz = noise_z + ((long)b * TT + t) * DD;
    float*       z  = Z + (long)r * DD;

    float4 hv = *reinterpret_cast<const float4*>(h + tid * 4);
    float s  = hv.x + hv.y + hv.z + hv.w;
    float ss = hv.x * hv.x + hv.y * hv.y + hv.z * hv.z + hv.w * hv.w;

    #pragma unroll
    for (int off = 16; off > 0; off >>= 1) {
        s  += __shfl_xor_sync(0xffffffffu, s,  off);
        ss += __shfl_xor_sync(0xffffffffu, ss, off);
    }
    __shared__ float ws[8], wss[8];
    const int lane = tid & 31, wrp = tid >> 5;
    if (lane == 0) { ws[wrp] = s; wss[wrp] = ss; }
    __syncthreads();

    float mu = 0.f, m2 = 0.f;
    #pragma unroll
    for (int i = 0; i < 8; i++) { mu += ws[i]; m2 += wss[i]; }
    mu *= (1.0f / DD);
    float var  = m2 * (1.0f / DD) - mu * mu;
    float rstd = rsqrtf(var + 1e-5f);

    float4 nv = *reinterpret_cast<const float4*>(nz + tid * 4);
    float4 g4 = *reinterpret_cast<const float4*>(gamma + tid * 4);
    float4 b4 = *reinterpret_cast<const float4*>(beta + tid * 4);

    const float fl = 1e-3f, gl = 1.0f - 1e-3f;
    float4 ov; float v;
    v = (hv.x - mu) * rstd * g4.x + b4.x; v = nv.x * fl + v * gl; ov.x = fminf(1.0f, fmaxf(-1.0f, v));
    v = (hv.y - mu) * rstd * g4.y + b4.y; v = nv.y * fl + v * gl; ov.y = fminf(1.0f, fmaxf(-1.0f, v));
    v = (hv.z - mu) * rstd * g4.z + b4.z; v = nv.z * fl + v * gl; ov.z = fminf(1.0f, fmaxf(-1.0f, v));
    v = (hv.w - mu) * rstd * g4.w + b4.w; v = nv.w * fl + v * gl; ov.w = fminf(1.0f, fmaxf(-1.0f, v));
    *reinterpret_cast<float4*>(z + tid * 4) = ov;
}

extern "C" void kernel_launch(void* const* d_in, const int* in_sizes, int n_in,
                              void* d_out, int out_size) {
    const float* x       = (const float*)d_in[0];
    const float* noise_x = (const float*)d_in[1];
    const float* noise_z = (const float*)d_in[2];
    const float* enc_w1  = (const float*)d_in[3];   // [T][C][D]
    const float* enc_w2  = (const float*)d_in[4];   // [T][D][D]
    const float* dec_w1  = (const float*)d_in[5];   // [T][D][D]
    const float* dec_w2  = (const float*)d_in[6];   // [T][D][C]
    const float* ln_g    = (const float*)d_in[7];
    const float* ln_b    = (const float*)d_in[8];
    float* out = (float*)d_out;

    float *XN, *H, *H2, *Z, *G;
    cudaGetSymbolAddress((void**)&XN, g_XN);
    cudaGetSymbolAddress((void**)&H,  g_H);
    cudaGetSymbolAddress((void**)&H2, g_H2);
    cudaGetSymbolAddress((void**)&Z,  g_Z);
    cudaGetSymbolAddress((void**)&G,  g_G);

    const int smem_bytes = SM_WORDS * 4;   // 53248
    cudaFuncSetAttribute(gemm_mma<true>,  cudaFuncAttributeMaxDynamicSharedMemorySize, smem_bytes);
    cudaFuncSetAttribute(gemm_mma<false>, cudaFuncAttributeMaxDynamicSharedMemorySize, smem_bytes);

    // 0) noise-mix x
    {
        int n4 = BB * TT * CC / 4;
        mix_kernel<<<n4 / 256, 256>>>(x, noise_x, XN, n4);
    }

    // 1) enc1: H = gelu(XN_chunk @ enc_w1[t])   K=2048, N=1024
    gemm_mma<true><<<dim3(DD / 128, TT), 256, smem_bytes>>>(
        XN, (long)CC, TT * CC, enc_w1, DD, CC, H, (long)BB * DD, DD);

    // 2) enc2: H2 = H @ enc_w2[t]               K=1024, N=1024
    gemm_mma<false><<<dim3(DD / 128, TT), 256, smem_bytes>>>(
        H, (long)BB * DD, DD, enc_w2, DD, DD, H2, (long)BB * DD, DD);

    // 3) LayerNorm + latent noise + clamp
    ln_kernel<<<TT * BB, 256>>>(H2, noise_z, ln_g, ln_b, Z);

    // 4) dec1: G = gelu(Z @ dec_w1[t])           K=1024, N=1024
    gemm_mma<true><<<dim3(DD / 128, TT), 256, smem_bytes>>>(
        Z, (long)BB * DD, DD, dec_w1, DD, DD, G, (long)BB * DD, DD);

    // 5) dec2: out = G @ dec_w2[t]               K=1024, N=2048
    gemm_mma<false><<<dim3(CC / 128, TT), 256, smem_bytes>>>(
        G, (long)BB * DD, DD, dec_w2, CC, DD, out, (long)CC, TT * CC);
}